// round 1
// baseline (speedup 1.0000x reference)
#include <cuda_runtime.h>
#include <math.h>

#define BATCH 32
#define HW    1024
#define CCH   256
#define FF    64

// Scratch (allocation-free: __device__ globals)
__device__ float g_emb[BATCH * HW * FF];     // 8 MB
__device__ float g_short[BATCH * HW * CCH];  // 32 MB
__device__ float g_T[BATCH * HW];
__device__ float g_sq[BATCH * HW];

__device__ __forceinline__ float dot4(float4 a, float4 b) {
    return a.x * b.x + a.y * b.y + a.z * b.z + a.w * b.w;
}

// ---------------------------------------------------------------------------
// Stage A: Y[N, OUT] = X[N, 256] @ W[OUT, 256]^T + bias
// block = 64 rows x 64 outs, 256 threads, 4x4 register tile
// ---------------------------------------------------------------------------
__global__ __launch_bounds__(256) void gemm_xwT(
    const float* __restrict__ X, const float* __restrict__ W,
    const float* __restrict__ bias, float* __restrict__ Y, int OUT)
{
    __shared__ float xs[64 * 68];
    __shared__ float ws[64 * 68];
    int tid  = threadIdx.x;
    int row0 = blockIdx.x * 64;
    int o0   = blockIdx.y * 64;
    int ty = tid >> 4, tx = tid & 15;
    float acc[4][4] = {};

    for (int kk = 0; kk < 256; kk += 64) {
        #pragma unroll
        for (int m = 0; m < 4; m++) {
            int idx = tid + m * 256;
            int r = idx >> 4, k4 = idx & 15;
            *(float4*)&xs[r * 68 + k4 * 4] =
                *(const float4*)&X[(size_t)(row0 + r) * 256 + kk + k4 * 4];
            *(float4*)&ws[r * 68 + k4 * 4] =
                *(const float4*)&W[(size_t)(o0 + r) * 256 + kk + k4 * 4];
        }
        __syncthreads();
        #pragma unroll
        for (int k4 = 0; k4 < 16; k4++) {
            float4 a[4], bb[4];
            #pragma unroll
            for (int i = 0; i < 4; i++) a[i]  = *(float4*)&xs[(ty + 16 * i) * 68 + k4 * 4];
            #pragma unroll
            for (int j = 0; j < 4; j++) bb[j] = *(float4*)&ws[(tx + 16 * j) * 68 + k4 * 4];
            #pragma unroll
            for (int i = 0; i < 4; i++) {
                #pragma unroll
                for (int j = 0; j < 4; j++) acc[i][j] += dot4(a[i], bb[j]);
            }
        }
        __syncthreads();
    }
    #pragma unroll
    for (int i = 0; i < 4; i++) {
        #pragma unroll
        for (int j = 0; j < 4; j++) {
            int o = o0 + tx + 16 * j;
            Y[(size_t)(row0 + ty + 16 * i) * OUT + o] = acc[i][j] + bias[o];
        }
    }
}

// ---------------------------------------------------------------------------
// Stage A2: per-row threshold T = shortcut . thr_W + thr_b, and sq = |emb|^2
// one warp per row
// ---------------------------------------------------------------------------
__global__ __launch_bounds__(256) void aux_kernel(
    const float* __restrict__ thrW, const float* __restrict__ thrb)
{
    int w = threadIdx.x >> 5, lane = threadIdx.x & 31;
    int row = blockIdx.x * 8 + w;  // 0..32767

    const float4* s4 = (const float4*)(g_short + (size_t)row * 256);
    const float4* t4 = (const float4*)thrW;
    float d = 0.f;
    #pragma unroll
    for (int m = 0; m < 2; m++) {
        float4 a = s4[lane + 32 * m], b = t4[lane + 32 * m];
        d += dot4(a, b);
    }
    float s = 0.f;
    if (lane < 16) {
        float4 e = ((const float4*)(g_emb + (size_t)row * 64))[lane];
        s = dot4(e, e);
    }
    #pragma unroll
    for (int off = 16; off; off >>= 1) {
        d += __shfl_xor_sync(0xffffffffu, d, off);
        s += __shfl_xor_sync(0xffffffffu, s, off);
    }
    if (lane == 0) { g_T[row] = d + thrb[0]; g_sq[row] = s; }
}

// ---------------------------------------------------------------------------
// Fused attention: one block = (batch b, 32-row tile). 512 threads (16 warps,
// 2 rows/warp). Two passes over j (1024), ev = exp(v) kept in smem.
// ---------------------------------------------------------------------------
#define SM_EI   32768           // ev [32][1024] at 0
#define SM_SC   (SM_EI + 32*68) // union: ej [64][68] / sc [64][256]
#define SM_W    (SM_SC + 64*256)
#define SM_T    (SM_W + 32*64)
#define SM_SQJ  (SM_T + 1024)
#define SM_TOT  (SM_SQJ + 64)   // = 54464 floats = 217856 B

__global__ __launch_bounds__(512) void fused_attn(
    const float* __restrict__ x, float* __restrict__ out)
{
    extern __shared__ float sm[];
    float* ev  = sm;
    float* ei  = sm + SM_EI;
    float* scs = sm + SM_SC;
    float* wb  = sm + SM_W;
    float* Ts  = sm + SM_T;
    float* sqj = sm + SM_SQJ;

    int tid  = threadIdx.x;
    int w    = tid >> 5, lane = tid & 31;
    int b    = blockIdx.y;
    int i0   = blockIdx.x * 32;
    int r0   = w * 2;

    {   // load emb tile for this block's 32 rows + all thresholds
        int r = tid >> 4, k4 = tid & 15;
        *(float4*)&ei[r * 68 + k4 * 4] =
            *(const float4*)&g_emb[((size_t)b * HW + i0 + r) * 64 + k4 * 4];
        Ts[tid]       = g_T[b * HW + tid];
        Ts[tid + 512] = g_T[b * HW + tid + 512];
    }
    float sqi0 = g_sq[b * HW + i0 + r0];
    float sqi1 = g_sq[b * HW + i0 + r0 + 1];
    __syncthreads();

    int gi0 = i0 + r0, gi1 = gi0 + 1;
    int yi0 = gi0 >> 5, xi0 = gi0 & 31;
    int yi1 = gi1 >> 5, xi1 = gi1 & 31;

    // ---------------- Pass 1: gram -> ev = exp(v), Z1 ----------------
    float z1p0 = 0.f, z1p1 = 0.f;
    for (int jt = 0; jt < 16; jt++) {
        int j0 = jt * 64;
        #pragma unroll
        for (int m = 0; m < 2; m++) {
            int idx = tid + m * 512;
            int r = idx >> 4, k4 = idx & 15;
            *(float4*)&scs[r * 68 + k4 * 4] =
                *(const float4*)&g_emb[((size_t)b * HW + j0 + r) * 64 + k4 * 4];
        }
        if (tid < 64) sqj[tid] = g_sq[b * HW + j0 + tid];
        __syncthreads();

        float a00 = 0.f, a01 = 0.f, a10 = 0.f, a11 = 0.f;
        #pragma unroll
        for (int k4 = 0; k4 < 16; k4++) {
            float4 u0 = *(float4*)&ei[r0 * 68 + k4 * 4];
            float4 u1 = *(float4*)&ei[(r0 + 1) * 68 + k4 * 4];
            float4 v0 = *(float4*)&scs[lane * 68 + k4 * 4];
            float4 v1 = *(float4*)&scs[(lane + 32) * 68 + k4 * 4];
            a00 += dot4(u0, v0); a01 += dot4(u0, v1);
            a10 += dot4(u1, v0); a11 += dot4(u1, v1);
        }
        {
            int c0 = lane, c1 = lane + 32;
            int gj0 = j0 + c0, gj1 = j0 + c1;
            float sj0 = sqj[c0], sj1 = sqj[c1];

            float d200 = fmaxf(sqi0 + sj0 - 2.f * a00, 0.f);
            float d201 = fmaxf(sqi0 + sj1 - 2.f * a01, 0.f);
            float d210 = fmaxf(sqi1 + sj0 - 2.f * a10, 0.f);
            float d211 = fmaxf(sqi1 + sj1 - 2.f * a11, 0.f);

            int yj0 = gj0 >> 5, xj0 = gj0 & 31;
            int yj1 = gj1 >> 5, xj1 = gj1 & 31;
            int df00 = abs(yi0 - yj0) + abs(xi0 - xj0);
            int df01 = abs(yi0 - yj1) + abs(xi0 - xj1);
            int df10 = abs(yi1 - yj0) + abs(xi1 - xj0);
            int df11 = abs(yi1 - yj1) + abs(xi1 - xj1);
            float m00 = (df00 <= 32) ? df00 * (1.f / 32.f) : 0.f;
            float m01 = (df01 <= 32) ? df01 * (1.f / 32.f) : 0.f;
            float m10 = (df10 <= 32) ? df10 * (1.f / 32.f) : 0.f;
            float m11 = (df11 <= 32) ? df11 * (1.f / 32.f) : 0.f;

            float e00 = __expf(__expf(-d200) + m00 - 1.f);
            float e01 = __expf(__expf(-d201) + m01 - 1.f);
            float e10 = __expf(__expf(-d210) + m10 - 1.f);
            float e11 = __expf(__expf(-d211) + m11 - 1.f);

            ev[r0 * 1024 + gj0]       = e00;
            ev[r0 * 1024 + gj1]       = e01;
            ev[(r0 + 1) * 1024 + gj0] = e10;
            ev[(r0 + 1) * 1024 + gj1] = e11;
            z1p0 += e00 + e01;
            z1p1 += e10 + e11;
        }
        __syncthreads();
    }
    #pragma unroll
    for (int off = 16; off; off >>= 1) {
        z1p0 += __shfl_xor_sync(0xffffffffu, z1p0, off);
        z1p1 += __shfl_xor_sync(0xffffffffu, z1p1, off);
    }
    float iz0 = 1.f / z1p0;
    float iz1 = 1.f / z1p1;

    // ---------------- Pass 2: w = exp(relu(sim - T_j)), Z2, P += w*sc ------
    float acc[2][8];
    #pragma unroll
    for (int i = 0; i < 2; i++)
        #pragma unroll
        for (int cc = 0; cc < 8; cc++) acc[i][cc] = 0.f;
    float z2p0 = 0.f, z2p1 = 0.f;

    for (int jt = 0; jt < 16; jt++) {
        int j0 = jt * 64;
        #pragma unroll
        for (int m = 0; m < 8; m++) {
            int idx = tid + m * 512;
            int rr = idx >> 6, k4 = idx & 63;
            *(float4*)&scs[rr * 256 + k4 * 4] =
                *(const float4*)&g_short[((size_t)b * HW + j0 + rr) * 256 + k4 * 4];
        }
        #pragma unroll
        for (int jj = 0; jj < 2; jj++) {
            int c = lane + 32 * jj;
            float t  = Ts[j0 + c];
            float s0 = ev[r0 * 1024 + j0 + c] * iz0;
            float s1 = ev[(r0 + 1) * 1024 + j0 + c] * iz1;
            float w0 = __expf(fmaxf(s0 - t, 0.f));
            float w1 = __expf(fmaxf(s1 - t, 0.f));
            wb[r0 * 64 + c]       = w0;
            wb[(r0 + 1) * 64 + c] = w1;
            z2p0 += w0;
            z2p1 += w1;
        }
        __syncthreads();

        #pragma unroll 4
        for (int k = 0; k < 64; k++) {
            float a0 = wb[r0 * 64 + k];
            float a1 = wb[(r0 + 1) * 64 + k];
            const float* sr = &scs[k * 256 + lane];
            #pragma unroll
            for (int cc = 0; cc < 8; cc++) {
                float bb = sr[cc * 32];
                acc[0][cc] = fmaf(a0, bb, acc[0][cc]);
                acc[1][cc] = fmaf(a1, bb, acc[1][cc]);
            }
        }
        __syncthreads();
    }
    #pragma unroll
    for (int off = 16; off; off >>= 1) {
        z2p0 += __shfl_xor_sync(0xffffffffu, z2p0, off);
        z2p1 += __shfl_xor_sync(0xffffffffu, z2p1, off);
    }
    float iz20 = 1.f / z2p0;
    float iz21 = 1.f / z2p1;

    size_t base = ((size_t)b * HW + i0 + r0) * 256 + lane;
    #pragma unroll
    for (int cc = 0; cc < 8; cc++) {
        int c = cc * 32;
        out[base + c]       = x[base + c]       + acc[0][cc] * iz20;
        out[base + 256 + c] = x[base + 256 + c] + acc[1][cc] * iz21;
    }
}

// ---------------------------------------------------------------------------
extern "C" void kernel_launch(void* const* d_in, const int* in_sizes, int n_in,
                              void* d_out, int out_size)
{
    (void)in_sizes; (void)n_in; (void)out_size;
    const float* x      = (const float*)d_in[0];
    const float* emb_W  = (const float*)d_in[1];
    const float* emb_b  = (const float*)d_in[2];
    const float* attn_W = (const float*)d_in[3];
    const float* attn_b = (const float*)d_in[4];
    const float* thr_W  = (const float*)d_in[5];
    const float* thr_b  = (const float*)d_in[6];
    float* out = (float*)d_out;

    float* emb_ptr = nullptr;
    float* short_ptr = nullptr;
    cudaGetSymbolAddress((void**)&emb_ptr, g_emb);
    cudaGetSymbolAddress((void**)&short_ptr, g_short);

    gemm_xwT<<<dim3(512, 1), 256>>>(x, emb_W, emb_b, emb_ptr, 64);
    gemm_xwT<<<dim3(512, 4), 256>>>(x, attn_W, attn_b, short_ptr, 256);
    aux_kernel<<<4096, 256>>>(thr_W, thr_b);

    cudaFuncSetAttribute(fused_attn,
                         cudaFuncAttributeMaxDynamicSharedMemorySize,
                         SM_TOT * sizeof(float));
    fused_attn<<<dim3(32, 32), 512, SM_TOT * sizeof(float)>>>(x, out);
}

// round 2
// speedup vs baseline: 1.2787x; 1.2787x over previous
#include <cuda_runtime.h>
#include <cuda_bf16.h>
#include <math.h>

#define BATCH 32
#define HW    1024
#define CCH   256
#define FF    64

// Scratch (allocation-free: __device__ globals)
__device__ float g_emb[BATCH * HW * FF];     // 8 MB
__device__ float g_short[BATCH * HW * CCH];  // 32 MB
__device__ float g_T[BATCH * HW];
__device__ float g_sq[BATCH * HW];

__device__ __forceinline__ float dot4(float4 a, float4 b) {
    return a.x * b.x + a.y * b.y + a.z * b.z + a.w * b.w;
}

// ---------------------------------------------------------------------------
// Stage A: Y[N, OUT] = X[N, 256] @ W[OUT, 256]^T + bias
// ---------------------------------------------------------------------------
__global__ __launch_bounds__(256) void gemm_xwT(
    const float* __restrict__ X, const float* __restrict__ W,
    const float* __restrict__ bias, float* __restrict__ Y, int OUT)
{
    __shared__ float xs[64 * 68];
    __shared__ float ws[64 * 68];
    int tid  = threadIdx.x;
    int row0 = blockIdx.x * 64;
    int o0   = blockIdx.y * 64;
    int ty = tid >> 4, tx = tid & 15;
    float acc[4][4] = {};

    for (int kk = 0; kk < 256; kk += 64) {
        #pragma unroll
        for (int m = 0; m < 4; m++) {
            int idx = tid + m * 256;
            int r = idx >> 4, k4 = idx & 15;
            *(float4*)&xs[r * 68 + k4 * 4] =
                *(const float4*)&X[(size_t)(row0 + r) * 256 + kk + k4 * 4];
            *(float4*)&ws[r * 68 + k4 * 4] =
                *(const float4*)&W[(size_t)(o0 + r) * 256 + kk + k4 * 4];
        }
        __syncthreads();
        #pragma unroll
        for (int k4 = 0; k4 < 16; k4++) {
            float4 a[4], bb[4];
            #pragma unroll
            for (int i = 0; i < 4; i++) a[i]  = *(float4*)&xs[(ty + 16 * i) * 68 + k4 * 4];
            #pragma unroll
            for (int j = 0; j < 4; j++) bb[j] = *(float4*)&ws[(tx + 16 * j) * 68 + k4 * 4];
            #pragma unroll
            for (int i = 0; i < 4; i++) {
                #pragma unroll
                for (int j = 0; j < 4; j++) acc[i][j] += dot4(a[i], bb[j]);
            }
        }
        __syncthreads();
    }
    #pragma unroll
    for (int i = 0; i < 4; i++) {
        #pragma unroll
        for (int j = 0; j < 4; j++) {
            int o = o0 + tx + 16 * j;
            Y[(size_t)(row0 + ty + 16 * i) * OUT + o] = acc[i][j] + bias[o];
        }
    }
}

// ---------------------------------------------------------------------------
// Stage A2: per-row threshold T and |emb|^2 — one warp per row
// ---------------------------------------------------------------------------
__global__ __launch_bounds__(256) void aux_kernel(
    const float* __restrict__ thrW, const float* __restrict__ thrb)
{
    int w = threadIdx.x >> 5, lane = threadIdx.x & 31;
    int row = blockIdx.x * 8 + w;

    const float4* s4 = (const float4*)(g_short + (size_t)row * 256);
    const float4* t4 = (const float4*)thrW;
    float d = 0.f;
    #pragma unroll
    for (int m = 0; m < 2; m++) {
        float4 a = s4[lane + 32 * m], b = t4[lane + 32 * m];
        d += dot4(a, b);
    }
    float s = 0.f;
    if (lane < 16) {
        float4 e = ((const float4*)(g_emb + (size_t)row * 64))[lane];
        s = dot4(e, e);
    }
    #pragma unroll
    for (int off = 16; off; off >>= 1) {
        d += __shfl_xor_sync(0xffffffffu, d, off);
        s += __shfl_xor_sync(0xffffffffu, s, off);
    }
    if (lane == 0) { g_T[row] = d + thrb[0]; g_sq[row] = s; }
}

// ---------------------------------------------------------------------------
// Fused attention v2: block = (batch, 32-row tile), 512 threads.
// ev stored bf16 (64KB); pass-1 j partitioned across threads (4 rows x 1 j);
// pass-2 GEMM register-tiled 4 rows x 4 cols; ~112.8 KB smem -> 2 blocks/SM.
// ---------------------------------------------------------------------------
#define SM_EI   16384                 // ev: bf16[32*1024] occupies sm[0 .. 16384)
#define SM_SCS  (SM_EI + 2048)        // ei: 32*64 fp32
#define SM_WT   (SM_SCS + 8192)       // scs: 32*256 fp32 (union ejs 64*68)
#define SM_TS   (SM_WT + 1024)        // wt: 32*32 (union sqs[1024])
#define SM_Z    (SM_TS + 1024)        // Ts: 1024
#define SM_TOT  (SM_Z + 192)          // z scratch

__global__ void __launch_bounds__(512, 2) fused_attn(
    const float* __restrict__ x, float* __restrict__ out)
{
    extern __shared__ float sm[];
    __nv_bfloat16* ev = (__nv_bfloat16*)sm;  // [32][1024]
    float* ei   = sm + SM_EI;                // [32][64]
    float* scs  = sm + SM_SCS;               // pass2: [32][256]; pass1: ejs [64][68]
    float* ejs  = scs;
    float* wsq  = sm + SM_WT;                // pass1: sqs[1024]; pass2: wt[32][32]
    float* Ts   = sm + SM_TS;                // [1024]
    float* izs  = sm + SM_Z;                 // [32]
    float* z2s  = izs + 32;                  // [32]
    float* zbuf = izs + 64;                  // [16][4]
    float* z2buf= izs + 128;                 // [16][2]

    int tid  = threadIdx.x;
    int lane = tid & 31;
    int w    = tid >> 5;
    int b    = blockIdx.y;
    int i0   = blockIdx.x * 32;

    // ---- prologue loads ----
    {
        int r = tid >> 4, k4 = tid & 15;
        *(float4*)&ei[r * 64 + k4 * 4] =
            *(const float4*)&g_emb[((size_t)b * HW + i0 + r) * 64 + k4 * 4];
    }
    wsq[tid]       = g_sq[b * HW + tid];
    wsq[tid + 512] = g_sq[b * HW + tid + 512];
    Ts[tid]        = g_T[b * HW + tid];
    Ts[tid + 512]  = g_T[b * HW + tid + 512];
    __syncthreads();

    // ---- pass 1: gram -> ev = exp(v) (bf16), Z1 ----
    int jl = tid & 63;      // j within 64-tile
    int rs = tid >> 6;      // rowset: 4 rows each
    float sqi[4]; int yi[4], xi[4];
    #pragma unroll
    for (int rr = 0; rr < 4; rr++) {
        int row = rs * 4 + rr;
        sqi[rr] = wsq[i0 + row];
        int gi = i0 + row;
        yi[rr] = gi >> 5; xi[rr] = gi & 31;
    }

    float z1p[4] = {0.f, 0.f, 0.f, 0.f};
    for (int jt = 0; jt < 16; jt++) {
        int j0 = jt * 64;
        #pragma unroll
        for (int m = 0; m < 2; m++) {
            int idx = tid + m * 512;
            int r = idx >> 4, k4 = idx & 15;
            *(float4*)&ejs[r * 68 + k4 * 4] =
                *(const float4*)&g_emb[((size_t)b * HW + j0 + r) * 64 + k4 * 4];
        }
        __syncthreads();

        float a[4] = {0.f, 0.f, 0.f, 0.f};
        #pragma unroll
        for (int k4 = 0; k4 < 16; k4++) {
            float4 bv = *(float4*)&ejs[jl * 68 + k4 * 4];
            #pragma unroll
            for (int rr = 0; rr < 4; rr++) {
                float4 av = *(float4*)&ei[(rs * 4 + rr) * 64 + k4 * 4];
                a[rr] += dot4(av, bv);
            }
        }

        int gj = j0 + jl;
        float sj = wsq[gj];
        int yj = gj >> 5, xj = gj & 31;
        #pragma unroll
        for (int rr = 0; rr < 4; rr++) {
            int row = rs * 4 + rr;
            float d2 = fmaxf(sqi[rr] + sj - 2.f * a[rr], 0.f);
            int df = abs(yi[rr] - yj) + abs(xi[rr] - xj);
            float msk = (df <= 32) ? df * (1.f / 32.f) : 0.f;
            float e = __expf(__expf(-d2) + msk - 1.f);
            ev[row * 1024 + gj] = __float2bfloat16(e);
            z1p[rr] += e;
        }
        __syncthreads();
    }
    // deterministic Z1 reduction: warp shuffle (all lanes share rowset) + smem
    #pragma unroll
    for (int off = 16; off; off >>= 1) {
        #pragma unroll
        for (int rr = 0; rr < 4; rr++)
            z1p[rr] += __shfl_xor_sync(0xffffffffu, z1p[rr], off);
    }
    if (lane == 0) {
        #pragma unroll
        for (int rr = 0; rr < 4; rr++) zbuf[w * 4 + rr] = z1p[rr];
    }
    __syncthreads();
    if (tid < 32) {
        int r = tid;
        float z = zbuf[(r >> 2) * 8 + (r & 3)] + zbuf[(r >> 2) * 8 + 4 + (r & 3)];
        izs[r] = 1.f / z;
    }
    __syncthreads();

    // ---- pass 2: w = exp(relu(sim - T_j)), Z2, P += w * shortcut ----
    int cg = tid & 63;   // 4-col group
    float4 acc[4];
    #pragma unroll
    for (int rr = 0; rr < 4; rr++) acc[rr] = make_float4(0.f, 0.f, 0.f, 0.f);
    float z2p[2] = {0.f, 0.f};

    for (int jt = 0; jt < 32; jt++) {
        int j0 = jt * 32;
        #pragma unroll
        for (int m = 0; m < 4; m++) {
            int idx = tid + m * 512;
            int r = idx >> 6, c4 = idx & 63;
            *(float4*)&scs[r * 256 + c4 * 4] =
                *(const float4*)&g_short[((size_t)b * HW + j0 + r) * 256 + c4 * 4];
        }
        // wt[row][k], rows w and w+16, k = lane
        #pragma unroll
        for (int e = 0; e < 2; e++) {
            int row = w + e * 16;
            float evf = __bfloat162float(ev[row * 1024 + j0 + lane]);
            float wv = __expf(fmaxf(evf * izs[row] - Ts[j0 + lane], 0.f));
            wsq[row * 32 + lane] = wv;
            z2p[e] += wv;
        }
        __syncthreads();

        #pragma unroll 8
        for (int k = 0; k < 32; k++) {
            float4 bv = *(float4*)&scs[k * 256 + cg * 4];
            #pragma unroll
            for (int rr = 0; rr < 4; rr++) {
                float av = wsq[(rs * 4 + rr) * 32 + k];
                acc[rr].x = fmaf(av, bv.x, acc[rr].x);
                acc[rr].y = fmaf(av, bv.y, acc[rr].y);
                acc[rr].z = fmaf(av, bv.z, acc[rr].z);
                acc[rr].w = fmaf(av, bv.w, acc[rr].w);
            }
        }
        __syncthreads();
    }
    // deterministic Z2 reduction
    #pragma unroll
    for (int off = 16; off; off >>= 1) {
        z2p[0] += __shfl_xor_sync(0xffffffffu, z2p[0], off);
        z2p[1] += __shfl_xor_sync(0xffffffffu, z2p[1], off);
    }
    if (lane == 0) { z2buf[w * 2] = z2p[0]; z2buf[w * 2 + 1] = z2p[1]; }
    __syncthreads();
    if (tid < 32) {
        int r = tid;
        float z = (r < 16) ? z2buf[r * 2] : z2buf[(r - 16) * 2 + 1];
        z2s[r] = 1.f / z;
    }
    __syncthreads();

    // ---- epilogue: out = x + P / Z2 ----
    #pragma unroll
    for (int rr = 0; rr < 4; rr++) {
        int row = rs * 4 + rr;
        float iz2 = z2s[row];
        size_t base = ((size_t)b * HW + i0 + row) * 256 + cg * 4;
        float4 xv = *(const float4*)&x[base];
        float4 o;
        o.x = xv.x + acc[rr].x * iz2;
        o.y = xv.y + acc[rr].y * iz2;
        o.z = xv.z + acc[rr].z * iz2;
        o.w = xv.w + acc[rr].w * iz2;
        *(float4*)&out[base] = o;
    }
}

// ---------------------------------------------------------------------------
extern "C" void kernel_launch(void* const* d_in, const int* in_sizes, int n_in,
                              void* d_out, int out_size)
{
    (void)in_sizes; (void)n_in; (void)out_size;
    const float* x      = (const float*)d_in[0];
    const float* emb_W  = (const float*)d_in[1];
    const float* emb_b  = (const float*)d_in[2];
    const float* attn_W = (const float*)d_in[3];
    const float* attn_b = (const float*)d_in[4];
    const float* thr_W  = (const float*)d_in[5];
    const float* thr_b  = (const float*)d_in[6];
    float* out = (float*)d_out;

    float* emb_ptr = nullptr;
    float* short_ptr = nullptr;
    cudaGetSymbolAddress((void**)&emb_ptr, g_emb);
    cudaGetSymbolAddress((void**)&short_ptr, g_short);

    gemm_xwT<<<dim3(512, 1), 256>>>(x, emb_W, emb_b, emb_ptr, 64);
    gemm_xwT<<<dim3(512, 4), 256>>>(x, attn_W, attn_b, short_ptr, 256);
    aux_kernel<<<4096, 256>>>(thr_W, thr_b);

    cudaFuncSetAttribute(fused_attn,
                         cudaFuncAttributeMaxDynamicSharedMemorySize,
                         SM_TOT * sizeof(float));
    fused_attn<<<dim3(32, 32), 512, SM_TOT * sizeof(float)>>>(x, out);
}

// round 6
// speedup vs baseline: 2.1697x; 1.6968x over previous
#include <cuda_runtime.h>
#include <cuda_bf16.h>
#include <cstdint>
#include <math.h>

#define BATCH 32
#define HW    1024
#define CCH   256
#define FF    64

// ---------------- scratch (allocation-free) ----------------
__device__ float g_emb[BATCH * HW * FF];           // 8 MB fp32 emb
__device__ float g_short[BATCH * HW * CCH];        // 32 MB fp32 shortcut
__device__ float g_T[BATCH * HW];
__device__ float g_sq[BATCH * HW];
__device__ float g_iz[BATCH * HW];
__device__ float g_z2[BATCH * HW];
__device__ __nv_bfloat16 g_ebh[BATCH * HW * FF];   // emb hi
__device__ __nv_bfloat16 g_ebl[BATCH * HW * FF];   // emb lo
__device__ __nv_bfloat16 g_sth[BATCH * CCH * HW];  // shortcut^T hi [b][c][j]
__device__ __nv_bfloat16 g_stl[BATCH * CCH * HW];  // shortcut^T lo
__device__ __nv_bfloat16 g_ev[BATCH * HW * HW];    // exp(v) [b][i][j]
__device__ __nv_bfloat16 g_wh[BATCH * HW * HW];    // w hi [b][i][j]
__device__ __nv_bfloat16 g_wl[BATCH * HW * HW];    // w lo

// ---------------- helpers ----------------
__device__ __forceinline__ uint32_t smem_u32(const void* p) {
    uint32_t a;
    asm("{ .reg .u64 t; cvta.to.shared.u64 t, %1; cvt.u32.u64 %0, t; }" : "=r"(a) : "l"(p));
    return a;
}
__device__ __forceinline__ void ldsm4(uint32_t& r0, uint32_t& r1, uint32_t& r2, uint32_t& r3,
                                      uint32_t addr) {
    asm volatile("ldmatrix.sync.aligned.m8n8.x4.shared.b16 {%0,%1,%2,%3}, [%4];"
        : "=r"(r0), "=r"(r1), "=r"(r2), "=r"(r3) : "r"(addr));
}
__device__ __forceinline__ void mma16816(float* d, const uint32_t* a, uint32_t b0, uint32_t b1) {
    asm volatile("mma.sync.aligned.m16n8k16.row.col.f32.bf16.bf16.f32 "
        "{%0,%1,%2,%3}, {%4,%5,%6,%7}, {%8,%9}, {%0,%1,%2,%3};"
        : "+f"(d[0]), "+f"(d[1]), "+f"(d[2]), "+f"(d[3])
        : "r"(a[0]), "r"(a[1]), "r"(a[2]), "r"(a[3]), "r"(b0), "r"(b1));
}
__device__ __forceinline__ uint32_t pack2bf(float a, float b) {
    __nv_bfloat162 t = __floats2bfloat162_rn(a, b);
    return *(uint32_t*)&t;
}
// stage a [128 rows x 64 bf16] tile into XOR-swizzled smem (rows of 128B)
__device__ __forceinline__ void stage_tile(char* dst, const __nv_bfloat16* src,
                                           int srcStride, int tid) {
    #pragma unroll
    for (int m = 0; m < 4; m++) {
        int idx = tid + m * 256;
        int row = idx >> 3, c4 = idx & 7;
        *(uint4*)(dst + row * 128 + ((c4 ^ (row & 7)) << 4)) =
            *(const uint4*)(src + (size_t)row * srcStride + c4 * 8);
    }
}

// ---------------------------------------------------------------------------
// Stage A: Y = X @ W^T + bias (generic, scalar — proven in R2)
// ---------------------------------------------------------------------------
__global__ __launch_bounds__(256) void gemm_xwT(
    const float* __restrict__ X, const float* __restrict__ W,
    const float* __restrict__ bias, float* __restrict__ Y, int OUT)
{
    __shared__ float xs[64 * 68];
    __shared__ float ws[64 * 68];
    int tid = threadIdx.x;
    int row0 = blockIdx.x * 64;
    int o0 = blockIdx.y * 64;
    int ty = tid >> 4, tx = tid & 15;
    float acc[4][4] = {};

    for (int kk = 0; kk < 256; kk += 64) {
        #pragma unroll
        for (int m = 0; m < 4; m++) {
            int idx = tid + m * 256;
            int r = idx >> 4, k4 = idx & 15;
            *(float4*)&xs[r * 68 + k4 * 4] =
                *(const float4*)&X[(size_t)(row0 + r) * 256 + kk + k4 * 4];
            *(float4*)&ws[r * 68 + k4 * 4] =
                *(const float4*)&W[(size_t)(o0 + r) * 256 + kk + k4 * 4];
        }
        __syncthreads();
        #pragma unroll
        for (int k4 = 0; k4 < 16; k4++) {
            float4 a[4], bb[4];
            #pragma unroll
            for (int i = 0; i < 4; i++) a[i] = *(float4*)&xs[(ty + 16 * i) * 68 + k4 * 4];
            #pragma unroll
            for (int j = 0; j < 4; j++) bb[j] = *(float4*)&ws[(tx + 16 * j) * 68 + k4 * 4];
            #pragma unroll
            for (int i = 0; i < 4; i++)
                #pragma unroll
                for (int j = 0; j < 4; j++)
                    acc[i][j] += a[i].x * bb[j].x + a[i].y * bb[j].y
                               + a[i].z * bb[j].z + a[i].w * bb[j].w;
        }
        __syncthreads();
    }
    #pragma unroll
    for (int i = 0; i < 4; i++)
        #pragma unroll
        for (int j = 0; j < 4; j++) {
            int o = o0 + tx + 16 * j;
            Y[(size_t)(row0 + ty + 16 * i) * OUT + o] = acc[i][j] + bias[o];
        }
}

// ---------------------------------------------------------------------------
// Stage A2: shortcut = X @ attn_W^T + b -> fp32 row-major + bf16 hi/lo TRANSPOSED
// ---------------------------------------------------------------------------
__global__ __launch_bounds__(256) void gemm_short(
    const float* __restrict__ X, const float* __restrict__ W,
    const float* __restrict__ bias)
{
    __shared__ float xs[64 * 68];
    __shared__ float ws[64 * 68];
    int tid = threadIdx.x;
    int row0 = blockIdx.x * 64;
    int o0 = blockIdx.y * 64;
    int ty = tid >> 4, tx = tid & 15;
    float acc[4][4] = {};

    for (int kk = 0; kk < 256; kk += 64) {
        #pragma unroll
        for (int m = 0; m < 4; m++) {
            int idx = tid + m * 256;
            int r = idx >> 4, k4 = idx & 15;
            *(float4*)&xs[r * 68 + k4 * 4] =
                *(const float4*)&X[(size_t)(row0 + r) * 256 + kk + k4 * 4];
            *(float4*)&ws[r * 68 + k4 * 4] =
                *(const float4*)&W[(size_t)(o0 + r) * 256 + kk + k4 * 4];
        }
        __syncthreads();
        #pragma unroll
        for (int k4 = 0; k4 < 16; k4++) {
            float4 a[4], bb[4];
            #pragma unroll
            for (int i = 0; i < 4; i++) a[i] = *(float4*)&xs[(ty + 16 * i) * 68 + k4 * 4];
            #pragma unroll
            for (int j = 0; j < 4; j++) bb[j] = *(float4*)&ws[(tx + 16 * j) * 68 + k4 * 4];
            #pragma unroll
            for (int i = 0; i < 4; i++)
                #pragma unroll
                for (int j = 0; j < 4; j++)
                    acc[i][j] += a[i].x * bb[j].x + a[i].y * bb[j].y
                               + a[i].z * bb[j].z + a[i].w * bb[j].w;
        }
        __syncthreads();
    }
    #pragma unroll
    for (int i = 0; i < 4; i++)
        #pragma unroll
        for (int j = 0; j < 4; j++) {
            int rl = ty + 16 * i, cl = tx + 16 * j;
            float v = acc[i][j] + bias[o0 + cl];
            g_short[(size_t)(row0 + rl) * 256 + o0 + cl] = v;
            xs[rl * 65 + cl] = v;
        }
    __syncthreads();
    // transposed hi/lo: thread -> (channel o_local, 16-row chunk)
    int ol = tid >> 2, ic = tid & 3;
    int b = row0 >> 10, il0 = (row0 & 1023) + ic * 16;
    size_t tb = ((size_t)b * CCH + o0 + ol) * HW + il0;
    #pragma unroll
    for (int ii = 0; ii < 16; ii++) {
        float v = xs[(ic * 16 + ii) * 65 + ol];
        __nv_bfloat16 hi = __float2bfloat16(v);
        g_sth[tb + ii] = hi;
        g_stl[tb + ii] = __float2bfloat16(v - __bfloat162float(hi));
    }
}

// ---------------------------------------------------------------------------
// Stage A3: T = shortcut.thr_W + b; |emb|^2; emb hi/lo split. One warp/row.
// ---------------------------------------------------------------------------
__global__ __launch_bounds__(256) void aux_kernel(
    const float* __restrict__ thrW, const float* __restrict__ thrb)
{
    int w = threadIdx.x >> 5, lane = threadIdx.x & 31;
    int row = blockIdx.x * 8 + w;
    const float4* s4 = (const float4*)(g_short + (size_t)row * 256);
    const float4* t4 = (const float4*)thrW;
    float d = 0.f;
    #pragma unroll
    for (int m = 0; m < 2; m++) {
        float4 a = s4[lane + 32 * m], b = t4[lane + 32 * m];
        d += a.x * b.x + a.y * b.y + a.z * b.z + a.w * b.w;
    }
    // emb split: 2 floats per lane
    float2 e = *(const float2*)&g_emb[(size_t)row * 64 + lane * 2];
    __nv_bfloat16 h0 = __float2bfloat16(e.x);
    __nv_bfloat16 h1 = __float2bfloat16(e.y);
    float l0 = e.x - __bfloat162float(h0);
    float l1 = e.y - __bfloat162float(h1);
    __nv_bfloat162 hp; hp.x = h0; hp.y = h1;
    ((uint32_t*)g_ebh)[row * 32 + lane] = *(uint32_t*)&hp;
    ((uint32_t*)g_ebl)[row * 32 + lane] = pack2bf(l0, l1);

    float s = e.x * e.x + e.y * e.y;
    #pragma unroll
    for (int off = 16; off; off >>= 1) {
        d += __shfl_xor_sync(0xffffffffu, d, off);
        s += __shfl_xor_sync(0xffffffffu, s, off);
    }
    if (lane == 0) { g_T[row] = d + thrb[0]; g_sq[row] = s; }
}

// ---------------------------------------------------------------------------
// K2: gram via HMMA (3-MMA bf16 split) -> ev = exp(exp(-d2)+mask-1), iz = 1/Z1
// block 128i x 128j, 8 warps (warp m32 x n64), k = 64.
// ---------------------------------------------------------------------------
#define G_AH 0
#define G_AL 16384
#define G_BH 32768
#define G_BL 49152
#define G_SQJ 65536
#define G_ZC  66048
#define G_SMEM (G_ZC + 1024)

__global__ void __launch_bounds__(256) gram_ev()
{
    extern __shared__ char smem[];
    uint32_t sb = smem_u32(smem);
    float* sqj = (float*)(smem + G_SQJ);
    float* zc  = (float*)(smem + G_ZC);
    int tid = threadIdx.x, lane = tid & 31, warp = tid >> 5;
    int wm = warp >> 1, wn = warp & 1;
    int g = lane >> 3, l7 = lane & 7, r = lane >> 2, q = lane & 3;
    int b = blockIdx.y, i0 = blockIdx.x * 128;

    stage_tile(smem + G_AH, g_ebh + ((size_t)b * HW + i0) * FF, FF, tid);
    stage_tile(smem + G_AL, g_ebl + ((size_t)b * HW + i0) * FF, FF, tid);

    float sqi[2][2];
    int yi[2][2], xi[2][2];
    #pragma unroll
    for (int mt = 0; mt < 2; mt++)
        #pragma unroll
        for (int hh = 0; hh < 2; hh++) {
            int il = wm * 32 + mt * 16 + r + hh * 8;
            sqi[mt][hh] = g_sq[b * HW + i0 + il];
            int gi = i0 + il;
            yi[mt][hh] = gi >> 5; xi[mt][hh] = gi & 31;
        }
    float z1a[2][2] = {{0.f, 0.f}, {0.f, 0.f}};

    for (int jc = 0; jc < 8; jc++) {
        int j0 = jc * 128;
        stage_tile(smem + G_BH, g_ebh + ((size_t)b * HW + j0) * FF, FF, tid);
        stage_tile(smem + G_BL, g_ebl + ((size_t)b * HW + j0) * FF, FF, tid);
        if (tid < 128) sqj[tid] = g_sq[b * HW + j0 + tid];
        __syncthreads();

        float acc[2][8][4];
        #pragma unroll
        for (int mt = 0; mt < 2; mt++)
            #pragma unroll
            for (int n = 0; n < 8; n++)
                #pragma unroll
                for (int c = 0; c < 4; c++) acc[mt][n][c] = 0.f;

        #pragma unroll
        for (int k = 0; k < 4; k++) {
            uint32_t ah[2][4], al[2][4];
            #pragma unroll
            for (int mt = 0; mt < 2; mt++) {
                int row = wm * 32 + mt * 16 + (g & 1) * 8 + l7;
                int c4 = k * 2 + (g >> 1);
                uint32_t off = row * 128 + ((c4 ^ (row & 7)) << 4);
                ldsm4(ah[mt][0], ah[mt][1], ah[mt][2], ah[mt][3], sb + G_AH + off);
                ldsm4(al[mt][0], al[mt][1], al[mt][2], al[mt][3], sb + G_AL + off);
            }
            uint32_t bh[4][4], bl[4][4];
            #pragma unroll
            for (int nt = 0; nt < 4; nt++) {
                int row = wn * 64 + nt * 16 + (g >> 1) * 8 + l7;
                int c4 = k * 2 + (g & 1);
                uint32_t off = row * 128 + ((c4 ^ (row & 7)) << 4);
                ldsm4(bh[nt][0], bh[nt][1], bh[nt][2], bh[nt][3], sb + G_BH + off);
                ldsm4(bl[nt][0], bl[nt][1], bl[nt][2], bl[nt][3], sb + G_BL + off);
            }
            #pragma unroll
            for (int mt = 0; mt < 2; mt++)
                #pragma unroll
                for (int nt = 0; nt < 4; nt++)
                    #pragma unroll
                    for (int h = 0; h < 2; h++) {
                        float* d = acc[mt][nt * 2 + h];
                        mma16816(d, ah[mt], bh[nt][h * 2], bh[nt][h * 2 + 1]);
                        mma16816(d, ah[mt], bl[nt][h * 2], bl[nt][h * 2 + 1]);
                        mma16816(d, al[mt], bh[nt][h * 2], bh[nt][h * 2 + 1]);
                    }
        }
        // epilogue
        #pragma unroll
        for (int mt = 0; mt < 2; mt++)
            #pragma unroll
            for (int nt8 = 0; nt8 < 8; nt8++) {
                int cloc = wn * 64 + nt8 * 8 + q * 2;
                int cj = j0 + cloc;
                float sj0 = sqj[cloc], sj1 = sqj[cloc + 1];
                int yj0 = cj >> 5, xj0 = cj & 31;
                int yj1 = (cj + 1) >> 5, xj1 = (cj + 1) & 31;
                #pragma unroll
                for (int hh = 0; hh < 2; hh++) {
                    int rowg = i0 + wm * 32 + mt * 16 + r + hh * 8;
                    float S0 = acc[mt][nt8][hh * 2 + 0];
                    float S1 = acc[mt][nt8][hh * 2 + 1];
                    float d20 = fmaxf(sqi[mt][hh] + sj0 - 2.f * S0, 0.f);
                    float d21 = fmaxf(sqi[mt][hh] + sj1 - 2.f * S1, 0.f);
                    int df0 = abs(yi[mt][hh] - yj0) + abs(xi[mt][hh] - xj0);
                    int df1 = abs(yi[mt][hh] - yj1) + abs(xi[mt][hh] - xj1);
                    float m0 = (df0 <= 32) ? df0 * (1.f / 32.f) : 0.f;
                    float m1 = (df1 <= 32) ? df1 * (1.f / 32.f) : 0.f;
                    float e0 = __expf(__expf(-d20) + m0 - 1.f);
                    float e1 = __expf(__expf(-d21) + m1 - 1.f);
                    z1a[mt][hh] += e0 + e1;
                    *(uint32_t*)&g_ev[((size_t)b * HW + rowg) * HW + cj] = pack2bf(e0, e1);
                }
            }
        __syncthreads();
    }
    #pragma unroll
    for (int mt = 0; mt < 2; mt++)
        #pragma unroll
        for (int hh = 0; hh < 2; hh++) {
            z1a[mt][hh] += __shfl_xor_sync(0xffffffffu, z1a[mt][hh], 1);
            z1a[mt][hh] += __shfl_xor_sync(0xffffffffu, z1a[mt][hh], 2);
        }
    if (q == 0) {
        #pragma unroll
        for (int mt = 0; mt < 2; mt++)
            #pragma unroll
            for (int hh = 0; hh < 2; hh++)
                zc[wn * 128 + wm * 32 + mt * 16 + r + hh * 8] = z1a[mt][hh];
    }
    __syncthreads();
    if (tid < 128)
        g_iz[b * HW + i0 + tid] = 1.f / (zc[tid] + zc[128 + tid]);
}

// ---------------------------------------------------------------------------
// K2b: w = exp(relu(ev*iz - T_j)) -> bf16 hi/lo + Z2. One warp per row.
// ---------------------------------------------------------------------------
__global__ __launch_bounds__(256) void wgen()
{
    int warp = threadIdx.x >> 5, lane = threadIdx.x & 31;
    int row = blockIdx.x * 8 + warp;          // global row 0..32767
    int b = row >> 10;
    float iz = g_iz[row];
    size_t evb = (size_t)row * HW;
    float z2 = 0.f;
    #pragma unroll
    for (int m = 0; m < 4; m++) {
        int j = m * 256 + lane * 8;
        uint4 eu = *(const uint4*)&g_ev[evb + j];
        float4 t0 = *(const float4*)&g_T[b * HW + j];
        float4 t1 = *(const float4*)&g_T[b * HW + j + 4];
        float tv[8] = {t0.x, t0.y, t0.z, t0.w, t1.x, t1.y, t1.z, t1.w};
        uint32_t eus[4] = {eu.x, eu.y, eu.z, eu.w};
        uint32_t hq[4], lq[4];
        #pragma unroll
        for (int p = 0; p < 4; p++) {
            __nv_bfloat162 e2 = *(__nv_bfloat162*)&eus[p];
            float w0 = __expf(fmaxf(fmaf(__bfloat162float(e2.x), iz, -tv[p * 2]), 0.f));
            float w1 = __expf(fmaxf(fmaf(__bfloat162float(e2.y), iz, -tv[p * 2 + 1]), 0.f));
            z2 += w0 + w1;
            __nv_bfloat16 h0 = __float2bfloat16(w0);
            __nv_bfloat16 h1 = __float2bfloat16(w1);
            __nv_bfloat162 hp; hp.x = h0; hp.y = h1;
            hq[p] = *(uint32_t*)&hp;
            lq[p] = pack2bf(w0 - __bfloat162float(h0), w1 - __bfloat162float(h1));
        }
        uint4 hu = {hq[0], hq[1], hq[2], hq[3]};
        uint4 lu = {lq[0], lq[1], lq[2], lq[3]};
        *(uint4*)&g_wh[evb + j] = hu;
        *(uint4*)&g_wl[evb + j] = lu;
    }
    #pragma unroll
    for (int off = 16; off; off >>= 1) z2 += __shfl_xor_sync(0xffffffffu, z2, off);
    if (lane == 0) g_z2[row] = z2;
}

// ---------------------------------------------------------------------------
// K3: out = x + (w @ shortcut) / Z2 via HMMA 3-split.
// block 128i x 128c, 8 warps (m32 x n64), k = 1024 in 16 chunks of 64.
// ---------------------------------------------------------------------------
#define O_AH 0
#define O_AL 16384
#define O_BH 32768
#define O_BL 49152
#define O_SMEM 65536

__global__ void __launch_bounds__(256) attn_out(
    const float* __restrict__ x, float* __restrict__ out)
{
    extern __shared__ char smem[];
    uint32_t sb = smem_u32(smem);
    int tid = threadIdx.x, lane = tid & 31, warp = tid >> 5;
    int wm = warp >> 1, wn = warp & 1;
    int g = lane >> 3, l7 = lane & 7, r = lane >> 2, q = lane & 3;
    int b = blockIdx.z, i0 = blockIdx.x * 128, c0 = blockIdx.y * 128;

    float acc[2][8][4];
    #pragma unroll
    for (int mt = 0; mt < 2; mt++)
        #pragma unroll
        for (int n = 0; n < 8; n++)
            #pragma unroll
            for (int c = 0; c < 4; c++) acc[mt][n][c] = 0.f;

    for (int kc = 0; kc < 16; kc++) {
        int j0 = kc * 64;
        stage_tile(smem + O_AH, g_wh + ((size_t)b * HW + i0) * HW + j0, HW, tid);
        stage_tile(smem + O_AL, g_wl + ((size_t)b * HW + i0) * HW + j0, HW, tid);
        stage_tile(smem + O_BH, g_sth + ((size_t)b * CCH + c0) * HW + j0, HW, tid);
        stage_tile(smem + O_BL, g_stl + ((size_t)b * CCH + c0) * HW + j0, HW, tid);
        __syncthreads();

        #pragma unroll
        for (int k = 0; k < 4; k++) {
            uint32_t ah[2][4], al[2][4];
            #pragma unroll
            for (int mt = 0; mt < 2; mt++) {
                int row = wm * 32 + mt * 16 + (g & 1) * 8 + l7;
                int c4 = k * 2 + (g >> 1);
                uint32_t off = row * 128 + ((c4 ^ (row & 7)) << 4);
                ldsm4(ah[mt][0], ah[mt][1], ah[mt][2], ah[mt][3], sb + O_AH + off);
                ldsm4(al[mt][0], al[mt][1], al[mt][2], al[mt][3], sb + O_AL + off);
            }
            uint32_t bh[4][4], bl[4][4];
            #pragma unroll
            for (int nt = 0; nt < 4; nt++) {
                int row = wn * 64 + nt * 16 + (g >> 1) * 8 + l7;
                int c4 = k * 2 + (g & 1);
                uint32_t off = row * 128 + ((c4 ^ (row & 7)) << 4);
                ldsm4(bh[nt][0], bh[nt][1], bh[nt][2], bh[nt][3], sb + O_BH + off);
                ldsm4(bl[nt][0], bl[nt][1], bl[nt][2], bl[nt][3], sb + O_BL + off);
            }
            #pragma unroll
            for (int mt = 0; mt < 2; mt++)
                #pragma unroll
                for (int nt = 0; nt < 4; nt++)
                    #pragma unroll
                    for (int h = 0; h < 2; h++) {
                        float* d = acc[mt][nt * 2 + h];
                        mma16816(d, ah[mt], bh[nt][h * 2], bh[nt][h * 2 + 1]);
                        mma16816(d, ah[mt], bl[nt][h * 2], bl[nt][h * 2 + 1]);
                        mma16816(d, al[mt], bh[nt][h * 2], bh[nt][h * 2 + 1]);
                    }
        }
        __syncthreads();
    }

    // epilogue: out = x + acc / z2
    #pragma unroll
    for (int mt = 0; mt < 2; mt++)
        #pragma unroll
        for (int hh = 0; hh < 2; hh++) {
            int rowg = i0 + wm * 32 + mt * 16 + r + hh * 8;
            float iz2 = 1.f / g_z2[b * HW + rowg];
            #pragma unroll
            for (int nt8 = 0; nt8 < 8; nt8++) {
                int col = c0 + wn * 64 + nt8 * 8 + q * 2;
                size_t base = ((size_t)b * HW + rowg) * CCH + col;
                float2 xv = *(const float2*)&x[base];
                float2 o;
                o.x = xv.x + acc[mt][nt8][hh * 2 + 0] * iz2;
                o.y = xv.y + acc[mt][nt8][hh * 2 + 1] * iz2;
                *(float2*)&out[base] = o;
            }
        }
}

// ---------------------------------------------------------------------------
extern "C" void kernel_launch(void* const* d_in, const int* in_sizes, int n_in,
                              void* d_out, int out_size)
{
    (void)in_sizes; (void)n_in; (void)out_size;
    const float* x      = (const float*)d_in[0];
    const float* emb_W  = (const float*)d_in[1];
    const float* emb_b  = (const float*)d_in[2];
    const float* attn_W = (const float*)d_in[3];
    const float* attn_b = (const float*)d_in[4];
    const float* thr_W  = (const float*)d_in[5];
    const float* thr_b  = (const float*)d_in[6];
    float* out = (float*)d_out;

    float* emb_ptr = nullptr;
    cudaGetSymbolAddress((void**)&emb_ptr, g_emb);

    gemm_xwT<<<dim3(512, 1), 256>>>(x, emb_W, emb_b, emb_ptr, 64);
    gemm_short<<<dim3(512, 4), 256>>>(x, attn_W, attn_b);
    aux_kernel<<<4096, 256>>>(thr_W, thr_b);

    cudaFuncSetAttribute(gram_ev, cudaFuncAttributeMaxDynamicSharedMemorySize, G_SMEM);
    gram_ev<<<dim3(8, 32), 256, G_SMEM>>>();

    wgen<<<4096, 256>>>();

    cudaFuncSetAttribute(attn_out, cudaFuncAttributeMaxDynamicSharedMemorySize, O_SMEM);
    attn_out<<<dim3(8, 2, 32), 256, O_SMEM>>>(x, out);
}

// round 7
// speedup vs baseline: 3.1261x; 1.4408x over previous
#include <cuda_runtime.h>
#include <cuda_bf16.h>
#include <cstdint>
#include <math.h>

#define BATCH 32
#define HW    1024
#define CCH   256
#define FF    64

// ---------------- scratch (allocation-free) ----------------
__device__ float g_emb[BATCH * HW * FF];
__device__ float g_short[BATCH * HW * CCH];
__device__ float g_T[BATCH * HW];
__device__ float g_sq[BATCH * HW];
__device__ float g_iz[BATCH * HW];
__device__ float g_z2[BATCH * HW];
__device__ __nv_bfloat16 g_xh[BATCH * HW * CCH];   // X hi
__device__ __nv_bfloat16 g_xl[BATCH * HW * CCH];   // X lo
__device__ __nv_bfloat16 g_wEh[FF * CCH];          // emb_W hi
__device__ __nv_bfloat16 g_wEl[FF * CCH];
__device__ __nv_bfloat16 g_wAh[CCH * CCH];         // attn_W hi
__device__ __nv_bfloat16 g_wAl[CCH * CCH];
__device__ __nv_bfloat16 g_ebh[BATCH * HW * FF];   // emb hi
__device__ __nv_bfloat16 g_ebl[BATCH * HW * FF];   // emb lo
__device__ __nv_bfloat16 g_sth[BATCH * CCH * HW];  // shortcut^T hi [b][c][j]
__device__ __nv_bfloat16 g_stl[BATCH * CCH * HW];  // shortcut^T lo
__device__ __nv_bfloat16 g_ev[BATCH * HW * HW];    // exp(v)
__device__ __nv_bfloat16 g_wh[BATCH * HW * HW];    // w hi
__device__ __nv_bfloat16 g_wl[BATCH * HW * HW];    // w lo

// ---------------- helpers ----------------
__device__ __forceinline__ uint32_t smem_u32(const void* p) {
    uint32_t a;
    asm("{ .reg .u64 t; cvta.to.shared.u64 t, %1; cvt.u32.u64 %0, t; }" : "=r"(a) : "l"(p));
    return a;
}
__device__ __forceinline__ void ldsm4(uint32_t& r0, uint32_t& r1, uint32_t& r2, uint32_t& r3,
                                      uint32_t addr) {
    asm volatile("ldmatrix.sync.aligned.m8n8.x4.shared.b16 {%0,%1,%2,%3}, [%4];"
        : "=r"(r0), "=r"(r1), "=r"(r2), "=r"(r3) : "r"(addr));
}
__device__ __forceinline__ void mma16816(float* d, const uint32_t* a, uint32_t b0, uint32_t b1) {
    asm volatile("mma.sync.aligned.m16n8k16.row.col.f32.bf16.bf16.f32 "
        "{%0,%1,%2,%3}, {%4,%5,%6,%7}, {%8,%9}, {%0,%1,%2,%3};"
        : "+f"(d[0]), "+f"(d[1]), "+f"(d[2]), "+f"(d[3])
        : "r"(a[0]), "r"(a[1]), "r"(a[2]), "r"(a[3]), "r"(b0), "r"(b1));
}
__device__ __forceinline__ uint32_t pack2bf(float a, float b) {
    __nv_bfloat162 t = __floats2bfloat162_rn(a, b);
    return *(uint32_t*)&t;
}
#define CPA(dst, src) asm volatile("cp.async.cg.shared.global [%0], [%1], 16;" :: "r"(dst), "l"(src))
#define CPC() asm volatile("cp.async.commit_group;" ::: "memory")
#define CPW(n) asm volatile("cp.async.wait_group %0;" :: "n"(n) : "memory")

// stage a [rows x 64 bf16] tile into XOR-swizzled smem (plain loads, for gram)
__device__ __forceinline__ void stage_tile(char* dst, const __nv_bfloat16* src,
                                           int srcStride, int tid) {
    #pragma unroll
    for (int m = 0; m < 4; m++) {
        int idx = tid + m * 256;
        int row = idx >> 3, c4 = idx & 7;
        *(uint4*)(dst + row * 128 + ((c4 ^ (row & 7)) << 4)) =
            *(const uint4*)(src + (size_t)row * srcStride + c4 * 8);
    }
}

// ---------------------------------------------------------------------------
// split fp32 -> bf16 hi/lo
// ---------------------------------------------------------------------------
__global__ __launch_bounds__(256) void split_f32(
    const float* __restrict__ src, __nv_bfloat16* __restrict__ hi,
    __nv_bfloat16* __restrict__ lo, int n4)
{
    int i = blockIdx.x * 256 + threadIdx.x;
    if (i >= n4) return;
    float4 v = ((const float4*)src)[i];
    __nv_bfloat16 h0 = __float2bfloat16(v.x);
    __nv_bfloat16 h1 = __float2bfloat16(v.y);
    __nv_bfloat16 h2 = __float2bfloat16(v.z);
    __nv_bfloat16 h3 = __float2bfloat16(v.w);
    __nv_bfloat162 hp0; hp0.x = h0; hp0.y = h1;
    __nv_bfloat162 hp1; hp1.x = h2; hp1.y = h3;
    uint2 hu = {*(uint32_t*)&hp0, *(uint32_t*)&hp1};
    uint2 lu = {pack2bf(v.x - __bfloat162float(h0), v.y - __bfloat162float(h1)),
                pack2bf(v.z - __bfloat162float(h2), v.w - __bfloat162float(h3))};
    ((uint2*)hi)[i] = hu;
    ((uint2*)lo)[i] = lu;
}

// ---------------------------------------------------------------------------
// hmma_emb: emb = X @ emb_W^T + b.  block 128 rows x 64 cols, 128 thr (4 warps).
// K=256 in 4 chunks of 64, cp.async double-buffered.
// stage layout: AH 0, AL 16384, BH 32768, BL 40960; stage size 49152.
// ---------------------------------------------------------------------------
#define E_ST 49152
__device__ __forceinline__ void emb_stage(uint32_t sb, int sofs, int i0, int kk, int tid) {
    #pragma unroll
    for (int m = 0; m < 8; m++) {
        int idx = tid + m * 128;
        int row = idx >> 3, c4 = idx & 7;
        uint32_t sw = row * 128 + ((c4 ^ (row & 7)) << 4);
        const __nv_bfloat16* sh = g_xh + (size_t)(i0 + row) * 256 + kk + c4 * 8;
        const __nv_bfloat16* sl = g_xl + (size_t)(i0 + row) * 256 + kk + c4 * 8;
        CPA(sb + sofs + 0 + sw, sh);
        CPA(sb + sofs + 16384 + sw, sl);
    }
    #pragma unroll
    for (int m = 0; m < 4; m++) {
        int idx = tid + m * 128;
        int row = idx >> 3, c4 = idx & 7;
        uint32_t sw = row * 128 + ((c4 ^ (row & 7)) << 4);
        CPA(sb + sofs + 32768 + sw, g_wEh + (size_t)row * 256 + kk + c4 * 8);
        CPA(sb + sofs + 40960 + sw, g_wEl + (size_t)row * 256 + kk + c4 * 8);
    }
}

__global__ void __launch_bounds__(128) hmma_emb(const float* __restrict__ bias)
{
    extern __shared__ char smem[];
    uint32_t sb = smem_u32(smem);
    int tid = threadIdx.x, lane = tid & 31, warp = tid >> 5;
    int g = lane >> 3, l7 = lane & 7, r = lane >> 2, q = lane & 3;
    int i0 = blockIdx.x * 128;
    int wm = warp;  // wn = 0

    float acc[2][8][4];
    #pragma unroll
    for (int mt = 0; mt < 2; mt++)
        #pragma unroll
        for (int n = 0; n < 8; n++)
            #pragma unroll
            for (int c = 0; c < 4; c++) acc[mt][n][c] = 0.f;

    emb_stage(sb, 0, i0, 0, tid); CPC();
    for (int kc = 0; kc < 4; kc++) {
        if (kc < 3) { emb_stage(sb, ((kc + 1) & 1) * E_ST, i0, (kc + 1) * 64, tid); CPC(); CPW(1); }
        else CPW(0);
        __syncthreads();
        int base = (kc & 1) * E_ST;
        #pragma unroll
        for (int k = 0; k < 4; k++) {
            uint32_t ah[2][4], al[2][4];
            #pragma unroll
            for (int mt = 0; mt < 2; mt++) {
                int row = wm * 32 + mt * 16 + (g & 1) * 8 + l7;
                int c4 = k * 2 + (g >> 1);
                uint32_t off = base + row * 128 + ((c4 ^ (row & 7)) << 4);
                ldsm4(ah[mt][0], ah[mt][1], ah[mt][2], ah[mt][3], sb + 0 + off);
                ldsm4(al[mt][0], al[mt][1], al[mt][2], al[mt][3], sb + 16384 + off);
            }
            uint32_t bh[4][4], bl[4][4];
            #pragma unroll
            for (int nt = 0; nt < 4; nt++) {
                int row = nt * 16 + (g >> 1) * 8 + l7;
                int c4 = k * 2 + (g & 1);
                uint32_t off = base + row * 128 + ((c4 ^ (row & 7)) << 4);
                ldsm4(bh[nt][0], bh[nt][1], bh[nt][2], bh[nt][3], sb + 32768 + off);
                ldsm4(bl[nt][0], bl[nt][1], bl[nt][2], bl[nt][3], sb + 40960 + off);
            }
            #pragma unroll
            for (int mt = 0; mt < 2; mt++)
                #pragma unroll
                for (int nt = 0; nt < 4; nt++)
                    #pragma unroll
                    for (int h = 0; h < 2; h++) {
                        float* d = acc[mt][nt * 2 + h];
                        mma16816(d, ah[mt], bh[nt][h * 2], bh[nt][h * 2 + 1]);
                        mma16816(d, ah[mt], bl[nt][h * 2], bl[nt][h * 2 + 1]);
                        mma16816(d, al[mt], bh[nt][h * 2], bh[nt][h * 2 + 1]);
                    }
        }
        __syncthreads();
    }
    // epilogue: +bias, write fp32 + bf16 hi/lo
    #pragma unroll
    for (int mt = 0; mt < 2; mt++)
        #pragma unroll
        for (int hh = 0; hh < 2; hh++) {
            int row = i0 + wm * 32 + mt * 16 + r + hh * 8;
            #pragma unroll
            for (int nt8 = 0; nt8 < 8; nt8++) {
                int col = nt8 * 8 + q * 2;
                float v0 = acc[mt][nt8][hh * 2 + 0] + bias[col];
                float v1 = acc[mt][nt8][hh * 2 + 1] + bias[col + 1];
                *(float2*)&g_emb[(size_t)row * 64 + col] = make_float2(v0, v1);
                __nv_bfloat16 h0 = __float2bfloat16(v0), h1 = __float2bfloat16(v1);
                __nv_bfloat162 hp; hp.x = h0; hp.y = h1;
                ((uint32_t*)g_ebh)[row * 32 + col / 2] = *(uint32_t*)&hp;
                ((uint32_t*)g_ebl)[row * 32 + col / 2] =
                    pack2bf(v0 - __bfloat162float(h0), v1 - __bfloat162float(h1));
            }
        }
}

// ---------------------------------------------------------------------------
// hmma_short: shortcut = X @ attn_W^T + b. block 128 rows x 128 cols, 256 thr.
// Epilogue: fp32 row-major + transposed bf16 hi/lo via smem transpose.
// stage layout: AH 0, AL 16384, BH 32768, BL 49152; stage size 65536.
// ---------------------------------------------------------------------------
#define S_ST 65536
__device__ __forceinline__ void short_stage(uint32_t sb, int sofs, int i0, int c0, int kk, int tid) {
    #pragma unroll
    for (int m = 0; m < 4; m++) {
        int idx = tid + m * 256;
        int row = idx >> 3, c4 = idx & 7;
        uint32_t sw = row * 128 + ((c4 ^ (row & 7)) << 4);
        CPA(sb + sofs + 0 + sw,     g_xh + (size_t)(i0 + row) * 256 + kk + c4 * 8);
        CPA(sb + sofs + 16384 + sw, g_xl + (size_t)(i0 + row) * 256 + kk + c4 * 8);
        CPA(sb + sofs + 32768 + sw, g_wAh + (size_t)(c0 + row) * 256 + kk + c4 * 8);
        CPA(sb + sofs + 49152 + sw, g_wAl + (size_t)(c0 + row) * 256 + kk + c4 * 8);
    }
}

__global__ void __launch_bounds__(256) hmma_short(const float* __restrict__ bias)
{
    extern __shared__ char smem[];
    uint32_t sb = smem_u32(smem);
    int tid = threadIdx.x, lane = tid & 31, warp = tid >> 5;
    int wm = warp >> 1, wn = warp & 1;
    int g = lane >> 3, l7 = lane & 7, r = lane >> 2, q = lane & 3;
    int i0 = blockIdx.x * 128, c0 = blockIdx.y * 128;
    int b = i0 >> 10;

    float acc[2][8][4];
    #pragma unroll
    for (int mt = 0; mt < 2; mt++)
        #pragma unroll
        for (int n = 0; n < 8; n++)
            #pragma unroll
            for (int c = 0; c < 4; c++) acc[mt][n][c] = 0.f;

    short_stage(sb, 0, i0, c0, 0, tid); CPC();
    for (int kc = 0; kc < 4; kc++) {
        if (kc < 3) { short_stage(sb, ((kc + 1) & 1) * S_ST, i0, c0, (kc + 1) * 64, tid); CPC(); CPW(1); }
        else CPW(0);
        __syncthreads();
        int base = (kc & 1) * S_ST;
        #pragma unroll
        for (int k = 0; k < 4; k++) {
            uint32_t ah[2][4], al[2][4];
            #pragma unroll
            for (int mt = 0; mt < 2; mt++) {
                int row = wm * 32 + mt * 16 + (g & 1) * 8 + l7;
                int c4 = k * 2 + (g >> 1);
                uint32_t off = base + row * 128 + ((c4 ^ (row & 7)) << 4);
                ldsm4(ah[mt][0], ah[mt][1], ah[mt][2], ah[mt][3], sb + 0 + off);
                ldsm4(al[mt][0], al[mt][1], al[mt][2], al[mt][3], sb + 16384 + off);
            }
            uint32_t bh[4][4], bl[4][4];
            #pragma unroll
            for (int nt = 0; nt < 4; nt++) {
                int row = wn * 64 + nt * 16 + (g >> 1) * 8 + l7;
                int c4 = k * 2 + (g & 1);
                uint32_t off = base + row * 128 + ((c4 ^ (row & 7)) << 4);
                ldsm4(bh[nt][0], bh[nt][1], bh[nt][2], bh[nt][3], sb + 32768 + off);
                ldsm4(bl[nt][0], bl[nt][1], bl[nt][2], bl[nt][3], sb + 49152 + off);
            }
            #pragma unroll
            for (int mt = 0; mt < 2; mt++)
                #pragma unroll
                for (int nt = 0; nt < 4; nt++)
                    #pragma unroll
                    for (int h = 0; h < 2; h++) {
                        float* d = acc[mt][nt * 2 + h];
                        mma16816(d, ah[mt], bh[nt][h * 2], bh[nt][h * 2 + 1]);
                        mma16816(d, ah[mt], bl[nt][h * 2], bl[nt][h * 2 + 1]);
                        mma16816(d, al[mt], bh[nt][h * 2], bh[nt][h * 2 + 1]);
                    }
        }
        __syncthreads();
    }

    // epilogue: +bias; fp32 to g_short; transpose via smem; bf16 hi/lo to g_sth/g_stl
    float* tb = (float*)smem;  // [128 cols][130] transpose buffer (66.5KB < 128KB)
    #pragma unroll
    for (int mt = 0; mt < 2; mt++)
        #pragma unroll
        for (int hh = 0; hh < 2; hh++) {
            int rl = wm * 32 + mt * 16 + r + hh * 8;
            #pragma unroll
            for (int nt8 = 0; nt8 < 8; nt8++) {
                int col = wn * 64 + nt8 * 8 + q * 2;
                float v0 = acc[mt][nt8][hh * 2 + 0] + bias[c0 + col];
                float v1 = acc[mt][nt8][hh * 2 + 1] + bias[c0 + col + 1];
                *(float2*)&g_short[(size_t)(i0 + rl) * 256 + c0 + col] = make_float2(v0, v1);
                tb[col * 130 + rl] = v0;
                tb[(col + 1) * 130 + rl] = v1;
            }
        }
    __syncthreads();
    {
        int c = tid >> 1, half = tid & 1;
        size_t tbase = ((size_t)b * CCH + c0 + c) * HW + (i0 & 1023) + half * 64;
        #pragma unroll
        for (int gch = 0; gch < 4; gch++) {
            uint32_t hp[8], lp[8];
            #pragma unroll
            for (int p = 0; p < 8; p++) {
                float v0 = tb[c * 130 + half * 64 + gch * 16 + p * 2];
                float v1 = tb[c * 130 + half * 64 + gch * 16 + p * 2 + 1];
                __nv_bfloat16 h0 = __float2bfloat16(v0), h1 = __float2bfloat16(v1);
                __nv_bfloat162 t; t.x = h0; t.y = h1;
                hp[p] = *(uint32_t*)&t;
                lp[p] = pack2bf(v0 - __bfloat162float(h0), v1 - __bfloat162float(h1));
            }
            *(uint4*)&g_sth[tbase + gch * 16]     = *(uint4*)&hp[0];
            *(uint4*)&g_sth[tbase + gch * 16 + 8] = *(uint4*)&hp[4];
            *(uint4*)&g_stl[tbase + gch * 16]     = *(uint4*)&lp[0];
            *(uint4*)&g_stl[tbase + gch * 16 + 8] = *(uint4*)&lp[4];
        }
    }
}

// ---------------------------------------------------------------------------
// aux: T = shortcut.thr_W + b; sq = |emb|^2. One warp per row.
// ---------------------------------------------------------------------------
__global__ __launch_bounds__(256) void aux_kernel(
    const float* __restrict__ thrW, const float* __restrict__ thrb)
{
    int w = threadIdx.x >> 5, lane = threadIdx.x & 31;
    int row = blockIdx.x * 8 + w;
    const float4* s4 = (const float4*)(g_short + (size_t)row * 256);
    const float4* t4 = (const float4*)thrW;
    float d = 0.f;
    #pragma unroll
    for (int m = 0; m < 2; m++) {
        float4 a = s4[lane + 32 * m], b = t4[lane + 32 * m];
        d += a.x * b.x + a.y * b.y + a.z * b.z + a.w * b.w;
    }
    float2 e = *(const float2*)&g_emb[(size_t)row * 64 + lane * 2];
    float s = e.x * e.x + e.y * e.y;
    #pragma unroll
    for (int off = 16; off; off >>= 1) {
        d += __shfl_xor_sync(0xffffffffu, d, off);
        s += __shfl_xor_sync(0xffffffffu, s, off);
    }
    if (lane == 0) { g_T[row] = d + thrb[0]; g_sq[row] = s; }
}

// ---------------------------------------------------------------------------
// gram_ev: HMMA 3-split gram -> ev = exp(exp(-d2)+mask-1), iz = 1/Z1
// ---------------------------------------------------------------------------
#define G_AH 0
#define G_AL 16384
#define G_BH 32768
#define G_BL 49152
#define G_SQJ 65536
#define G_ZC  66048
#define G_SMEM (G_ZC + 1024)

__global__ void __launch_bounds__(256) gram_ev()
{
    extern __shared__ char smem[];
    uint32_t sb = smem_u32(smem);
    float* sqj = (float*)(smem + G_SQJ);
    float* zc  = (float*)(smem + G_ZC);
    int tid = threadIdx.x, lane = tid & 31, warp = tid >> 5;
    int wm = warp >> 1, wn = warp & 1;
    int g = lane >> 3, l7 = lane & 7, r = lane >> 2, q = lane & 3;
    int b = blockIdx.y, i0 = blockIdx.x * 128;

    stage_tile(smem + G_AH, g_ebh + ((size_t)b * HW + i0) * FF, FF, tid);
    stage_tile(smem + G_AL, g_ebl + ((size_t)b * HW + i0) * FF, FF, tid);

    float sqi[2][2];
    int yi[2][2], xi[2][2];
    #pragma unroll
    for (int mt = 0; mt < 2; mt++)
        #pragma unroll
        for (int hh = 0; hh < 2; hh++) {
            int il = wm * 32 + mt * 16 + r + hh * 8;
            sqi[mt][hh] = g_sq[b * HW + i0 + il];
            int gi = i0 + il;
            yi[mt][hh] = gi >> 5; xi[mt][hh] = gi & 31;
        }
    float z1a[2][2] = {{0.f, 0.f}, {0.f, 0.f}};

    for (int jc = 0; jc < 8; jc++) {
        int j0 = jc * 128;
        stage_tile(smem + G_BH, g_ebh + ((size_t)b * HW + j0) * FF, FF, tid);
        stage_tile(smem + G_BL, g_ebl + ((size_t)b * HW + j0) * FF, FF, tid);
        if (tid < 128) sqj[tid] = g_sq[b * HW + j0 + tid];
        __syncthreads();

        float acc[2][8][4];
        #pragma unroll
        for (int mt = 0; mt < 2; mt++)
            #pragma unroll
            for (int n = 0; n < 8; n++)
                #pragma unroll
                for (int c = 0; c < 4; c++) acc[mt][n][c] = 0.f;

        #pragma unroll
        for (int k = 0; k < 4; k++) {
            uint32_t ah[2][4], al[2][4];
            #pragma unroll
            for (int mt = 0; mt < 2; mt++) {
                int row = wm * 32 + mt * 16 + (g & 1) * 8 + l7;
                int c4 = k * 2 + (g >> 1);
                uint32_t off = row * 128 + ((c4 ^ (row & 7)) << 4);
                ldsm4(ah[mt][0], ah[mt][1], ah[mt][2], ah[mt][3], sb + G_AH + off);
                ldsm4(al[mt][0], al[mt][1], al[mt][2], al[mt][3], sb + G_AL + off);
            }
            uint32_t bh[4][4], bl[4][4];
            #pragma unroll
            for (int nt = 0; nt < 4; nt++) {
                int row = wn * 64 + nt * 16 + (g >> 1) * 8 + l7;
                int c4 = k * 2 + (g & 1);
                uint32_t off = row * 128 + ((c4 ^ (row & 7)) << 4);
                ldsm4(bh[nt][0], bh[nt][1], bh[nt][2], bh[nt][3], sb + G_BH + off);
                ldsm4(bl[nt][0], bl[nt][1], bl[nt][2], bl[nt][3], sb + G_BL + off);
            }
            #pragma unroll
            for (int mt = 0; mt < 2; mt++)
                #pragma unroll
                for (int nt = 0; nt < 4; nt++)
                    #pragma unroll
                    for (int h = 0; h < 2; h++) {
                        float* d = acc[mt][nt * 2 + h];
                        mma16816(d, ah[mt], bh[nt][h * 2], bh[nt][h * 2 + 1]);
                        mma16816(d, ah[mt], bl[nt][h * 2], bl[nt][h * 2 + 1]);
                        mma16816(d, al[mt], bh[nt][h * 2], bh[nt][h * 2 + 1]);
                    }
        }
        #pragma unroll
        for (int mt = 0; mt < 2; mt++)
            #pragma unroll
            for (int nt8 = 0; nt8 < 8; nt8++) {
                int cloc = wn * 64 + nt8 * 8 + q * 2;
                int cj = j0 + cloc;
                float sj0 = sqj[cloc], sj1 = sqj[cloc + 1];
                int yj0 = cj >> 5, xj0 = cj & 31;
                int yj1 = (cj + 1) >> 5, xj1 = (cj + 1) & 31;
                #pragma unroll
                for (int hh = 0; hh < 2; hh++) {
                    int rowg = i0 + wm * 32 + mt * 16 + r + hh * 8;
                    float S0 = acc[mt][nt8][hh * 2 + 0];
                    float S1 = acc[mt][nt8][hh * 2 + 1];
                    float d20 = fmaxf(sqi[mt][hh] + sj0 - 2.f * S0, 0.f);
                    float d21 = fmaxf(sqi[mt][hh] + sj1 - 2.f * S1, 0.f);
                    int df0 = abs(yi[mt][hh] - yj0) + abs(xi[mt][hh] - xj0);
                    int df1 = abs(yi[mt][hh] - yj1) + abs(xi[mt][hh] - xj1);
                    float m0 = (df0 <= 32) ? df0 * (1.f / 32.f) : 0.f;
                    float m1 = (df1 <= 32) ? df1 * (1.f / 32.f) : 0.f;
                    float e0 = __expf(__expf(-d20) + m0 - 1.f);
                    float e1 = __expf(__expf(-d21) + m1 - 1.f);
                    z1a[mt][hh] += e0 + e1;
                    *(uint32_t*)&g_ev[((size_t)b * HW + rowg) * HW + cj] = pack2bf(e0, e1);
                }
            }
        __syncthreads();
    }
    #pragma unroll
    for (int mt = 0; mt < 2; mt++)
        #pragma unroll
        for (int hh = 0; hh < 2; hh++) {
            z1a[mt][hh] += __shfl_xor_sync(0xffffffffu, z1a[mt][hh], 1);
            z1a[mt][hh] += __shfl_xor_sync(0xffffffffu, z1a[mt][hh], 2);
        }
    if (q == 0) {
        #pragma unroll
        for (int mt = 0; mt < 2; mt++)
            #pragma unroll
            for (int hh = 0; hh < 2; hh++)
                zc[wn * 128 + wm * 32 + mt * 16 + r + hh * 8] = z1a[mt][hh];
    }
    __syncthreads();
    if (tid < 128)
        g_iz[b * HW + i0 + tid] = 1.f / (zc[tid] + zc[128 + tid]);
}

// ---------------------------------------------------------------------------
// wgen: w = exp(relu(ev*iz - T_j)) -> bf16 hi/lo + Z2. One warp per row.
// ---------------------------------------------------------------------------
__global__ __launch_bounds__(256) void wgen()
{
    int warp = threadIdx.x >> 5, lane = threadIdx.x & 31;
    int row = blockIdx.x * 8 + warp;
    int b = row >> 10;
    float iz = g_iz[row];
    size_t evb = (size_t)row * HW;
    float z2 = 0.f;
    #pragma unroll
    for (int m = 0; m < 4; m++) {
        int j = m * 256 + lane * 8;
        uint4 eu = *(const uint4*)&g_ev[evb + j];
        float4 t0 = *(const float4*)&g_T[b * HW + j];
        float4 t1 = *(const float4*)&g_T[b * HW + j + 4];
        float tv[8] = {t0.x, t0.y, t0.z, t0.w, t1.x, t1.y, t1.z, t1.w};
        uint32_t eus[4] = {eu.x, eu.y, eu.z, eu.w};
        uint32_t hq[4], lq[4];
        #pragma unroll
        for (int p = 0; p < 4; p++) {
            __nv_bfloat162 e2 = *(__nv_bfloat162*)&eus[p];
            float w0 = __expf(fmaxf(fmaf(__bfloat162float(e2.x), iz, -tv[p * 2]), 0.f));
            float w1 = __expf(fmaxf(fmaf(__bfloat162float(e2.y), iz, -tv[p * 2 + 1]), 0.f));
            z2 += w0 + w1;
            __nv_bfloat16 h0 = __float2bfloat16(w0);
            __nv_bfloat16 h1 = __float2bfloat16(w1);
            __nv_bfloat162 hp; hp.x = h0; hp.y = h1;
            hq[p] = *(uint32_t*)&hp;
            lq[p] = pack2bf(w0 - __bfloat162float(h0), w1 - __bfloat162float(h1));
        }
        uint4 hu = {hq[0], hq[1], hq[2], hq[3]};
        uint4 lu = {lq[0], lq[1], lq[2], lq[3]};
        *(uint4*)&g_wh[evb + j] = hu;
        *(uint4*)&g_wl[evb + j] = lu;
    }
    #pragma unroll
    for (int off = 16; off; off >>= 1) z2 += __shfl_xor_sync(0xffffffffu, z2, off);
    if (lane == 0) g_z2[row] = z2;
}

// ---------------------------------------------------------------------------
// attn_out: out = x + (w @ shortcut) / Z2, HMMA 3-split, cp.async double-buffer.
// ---------------------------------------------------------------------------
#define O_AH 0
#define O_AL 16384
#define O_BH 32768
#define O_BL 49152
#define O_ST 65536
__device__ __forceinline__ void k3_stage(uint32_t sb, int sofs, int b, int i0, int c0,
                                         int j0, int tid) {
    #pragma unroll
    for (int m = 0; m < 4; m++) {
        int idx = tid + m * 256;
        int row = idx >> 3, c4 = idx & 7;
        uint32_t sw = row * 128 + ((c4 ^ (row & 7)) << 4);
        CPA(sb + sofs + O_AH + sw, g_wh  + ((size_t)b * HW + i0 + row) * HW + j0 + c4 * 8);
        CPA(sb + sofs + O_AL + sw, g_wl  + ((size_t)b * HW + i0 + row) * HW + j0 + c4 * 8);
        CPA(sb + sofs + O_BH + sw, g_sth + ((size_t)b * CCH + c0 + row) * HW + j0 + c4 * 8);
        CPA(sb + sofs + O_BL + sw, g_stl + ((size_t)b * CCH + c0 + row) * HW + j0 + c4 * 8);
    }
}

__global__ void __launch_bounds__(256) attn_out(
    const float* __restrict__ x, float* __restrict__ out)
{
    extern __shared__ char smem[];
    uint32_t sb = smem_u32(smem);
    int tid = threadIdx.x, lane = tid & 31, warp = tid >> 5;
    int wm = warp >> 1, wn = warp & 1;
    int g = lane >> 3, l7 = lane & 7, r = lane >> 2, q = lane & 3;
    int b = blockIdx.z, i0 = blockIdx.x * 128, c0 = blockIdx.y * 128;

    float acc[2][8][4];
    #pragma unroll
    for (int mt = 0; mt < 2; mt++)
        #pragma unroll
        for (int n = 0; n < 8; n++)
            #pragma unroll
            for (int c = 0; c < 4; c++) acc[mt][n][c] = 0.f;

    k3_stage(sb, 0, b, i0, c0, 0, tid); CPC();
    for (int kc = 0; kc < 16; kc++) {
        if (kc < 15) { k3_stage(sb, ((kc + 1) & 1) * O_ST, b, i0, c0, (kc + 1) * 64, tid); CPC(); CPW(1); }
        else CPW(0);
        __syncthreads();
        int base = (kc & 1) * O_ST;
        #pragma unroll
        for (int k = 0; k < 4; k++) {
            uint32_t ah[2][4], al[2][4];
            #pragma unroll
            for (int mt = 0; mt < 2; mt++) {
                int row = wm * 32 + mt * 16 + (g & 1) * 8 + l7;
                int c4 = k * 2 + (g >> 1);
                uint32_t off = base + row * 128 + ((c4 ^ (row & 7)) << 4);
                ldsm4(ah[mt][0], ah[mt][1], ah[mt][2], ah[mt][3], sb + O_AH + off);
                ldsm4(al[mt][0], al[mt][1], al[mt][2], al[mt][3], sb + O_AL + off);
            }
            uint32_t bh[4][4], bl[4][4];
            #pragma unroll
            for (int nt = 0; nt < 4; nt++) {
                int row = wn * 64 + nt * 16 + (g >> 1) * 8 + l7;
                int c4 = k * 2 + (g & 1);
                uint32_t off = base + row * 128 + ((c4 ^ (row & 7)) << 4);
                ldsm4(bh[nt][0], bh[nt][1], bh[nt][2], bh[nt][3], sb + O_BH + off);
                ldsm4(bl[nt][0], bl[nt][1], bl[nt][2], bl[nt][3], sb + O_BL + off);
            }
            #pragma unroll
            for (int mt = 0; mt < 2; mt++)
                #pragma unroll
                for (int nt = 0; nt < 4; nt++)
                    #pragma unroll
                    for (int h = 0; h < 2; h++) {
                        float* d = acc[mt][nt * 2 + h];
                        mma16816(d, ah[mt], bh[nt][h * 2], bh[nt][h * 2 + 1]);
                        mma16816(d, ah[mt], bl[nt][h * 2], bl[nt][h * 2 + 1]);
                        mma16816(d, al[mt], bh[nt][h * 2], bh[nt][h * 2 + 1]);
                    }
        }
        __syncthreads();
    }

    #pragma unroll
    for (int mt = 0; mt < 2; mt++)
        #pragma unroll
        for (int hh = 0; hh < 2; hh++) {
            int rowg = i0 + wm * 32 + mt * 16 + r + hh * 8;
            float iz2 = 1.f / g_z2[b * HW + rowg];
            #pragma unroll
            for (int nt8 = 0; nt8 < 8; nt8++) {
                int col = c0 + wn * 64 + nt8 * 8 + q * 2;
                size_t base = ((size_t)b * HW + rowg) * CCH + col;
                float2 xv = *(const float2*)&x[base];
                float2 o;
                o.x = xv.x + acc[mt][nt8][hh * 2 + 0] * iz2;
                o.y = xv.y + acc[mt][nt8][hh * 2 + 1] * iz2;
                *(float2*)&out[base] = o;
            }
        }
}

// ---------------------------------------------------------------------------
extern "C" void kernel_launch(void* const* d_in, const int* in_sizes, int n_in,
                              void* d_out, int out_size)
{
    (void)in_sizes; (void)n_in; (void)out_size;
    const float* x      = (const float*)d_in[0];
    const float* emb_W  = (const float*)d_in[1];
    const float* emb_b  = (const float*)d_in[2];
    const float* attn_W = (const float*)d_in[3];
    const float* attn_b = (const float*)d_in[4];
    const float* thr_W  = (const float*)d_in[5];
    const float* thr_b  = (const float*)d_in[6];
    float* out = (float*)d_out;

    __nv_bfloat16 *xh, *xl, *wEh, *wEl, *wAh, *wAl;
    cudaGetSymbolAddress((void**)&xh,  g_xh);
    cudaGetSymbolAddress((void**)&xl,  g_xl);
    cudaGetSymbolAddress((void**)&wEh, g_wEh);
    cudaGetSymbolAddress((void**)&wEl, g_wEl);
    cudaGetSymbolAddress((void**)&wAh, g_wAh);
    cudaGetSymbolAddress((void**)&wAl, g_wAl);

    split_f32<<<8192, 256>>>(x, xh, xl, BATCH * HW * CCH / 4);
    split_f32<<<16, 256>>>(emb_W, wEh, wEl, FF * CCH / 4);
    split_f32<<<64, 256>>>(attn_W, wAh, wAl, CCH * CCH / 4);

    cudaFuncSetAttribute(hmma_emb, cudaFuncAttributeMaxDynamicSharedMemorySize, 2 * E_ST);
    hmma_emb<<<256, 128, 2 * E_ST>>>(emb_b);

    cudaFuncSetAttribute(hmma_short, cudaFuncAttributeMaxDynamicSharedMemorySize, 2 * S_ST);
    hmma_short<<<dim3(256, 2), 256, 2 * S_ST>>>(attn_b);

    aux_kernel<<<4096, 256>>>(thr_W, thr_b);

    cudaFuncSetAttribute(gram_ev, cudaFuncAttributeMaxDynamicSharedMemorySize, G_SMEM);
    gram_ev<<<dim3(8, 32), 256, G_SMEM>>>();

    wgen<<<4096, 256>>>();

    cudaFuncSetAttribute(attn_out, cudaFuncAttributeMaxDynamicSharedMemorySize, 2 * O_ST);
    attn_out<<<dim3(8, 2, 32), 256, 2 * O_ST>>>(x, out);
}